// round 11
// baseline (speedup 1.0000x reference)
#include <cuda_runtime.h>
#include <cuda_bf16.h>

#define BB 4
#define NBND 262144
#define NATM 8192
#define FF 32

typedef unsigned long long u64;

__device__ float g_bta[BB * NATM * FF];
__device__ float g_cnt[BB * NATM];
__device__ float g_bond_sum[BB * FF];
__device__ float g_atom_sum[BB * FF];
__device__ __align__(16) float g_pa[BB * NATM * 64];  // hst + atoms@W1[0:32]
__device__ __align__(16) float g_pb[BB * NATM * 64];  // atoms@W1[32:64]

__device__ __forceinline__ float softplus(float x) {
    return fmaxf(x, 0.0f) + __logf(1.0f + __expf(-fabsf(x)));
}
__device__ __forceinline__ u64 pack2(float lo, float hi) {
    u64 r; asm("mov.b64 %0, {%1, %2};" : "=l"(r) : "f"(lo), "f"(hi)); return r;
}
__device__ __forceinline__ u64 pack2s(float x) { return pack2(x, x); }
__device__ __forceinline__ void unpack2(u64 v, float& lo, float& hi) {
    asm("mov.b64 {%0, %1}, %2;" : "=f"(lo), "=f"(hi) : "l"(v));
}
__device__ __forceinline__ void fma2(u64& d, u64 a, u64 b) {
    asm("fma.rn.f32x2 %0, %1, %2, %0;" : "+l"(d) : "l"(a), "l"(b));
}
__device__ __forceinline__ void red4(float* p, float a, float b, float c, float d) {
    asm volatile("red.global.add.v4.f32 [%0], {%1, %2, %3, %4};"
                 :: "l"(p), "f"(a), "f"(b), "f"(c), "f"(d) : "memory");
}

__global__ void zero_kernel() {
    long i = (long)blockIdx.x * 256 + threadIdx.x;
    if (i < (long)BB * NATM * FF) g_bta[i] = 0.0f;
    if (i < BB * NATM) g_cnt[i] = 0.0f;
    if (i < BB * FF) { g_bond_sum[i] = 0.0f; g_atom_sum[i] = 0.0f; }
}

// per-atom projections pa/pb (1 thread = 1 atom); hst computed in-block
__global__ void __launch_bounds__(128) atom_pre_kernel(
    const float* __restrict__ atoms, const float* __restrict__ w1,
    const float* __restrict__ b1, const float* __restrict__ state)
{
    __shared__ __align__(16) float s_w[64 * 64];
    __shared__ __align__(16) float s_hst[64];
    const int tid = threadIdx.x;
    const int idx = blockIdx.x * 128 + tid;
    const int b = idx / NATM;
    for (int i = tid; i < 64 * 64; i += 128) s_w[i] = w1[i];
    if (tid < 64) {
        float acc = __ldg(&b1[tid]);
        #pragma unroll
        for (int k = 0; k < 32; k++)
            acc = fmaf(__ldg(&state[b * FF + k]), __ldg(&w1[(96 + k) * 64 + tid]), acc);
        s_hst[tid] = acc;
    }
    __syncthreads();

    float4 xv[8];
    const float4* p = (const float4*)(atoms + (long)idx * FF);
    #pragma unroll
    for (int q = 0; q < 8; q++) xv[q] = __ldg(&p[q]);
    const float* xf = (const float*)xv;

    u64 h[32];
    const u64* hstp = (const u64*)s_hst;
    #pragma unroll
    for (int j = 0; j < 32; j++) h[j] = hstp[j];
    #pragma unroll
    for (int k = 0; k < 32; k++) {
        const u64 xk2 = pack2s(xf[k]);
        const ulonglong2* wr = (const ulonglong2*)&s_w[k * 64];
        #pragma unroll
        for (int j = 0; j < 16; j++) {
            ulonglong2 w = wr[j];
            fma2(h[2 * j], xk2, w.x);
            fma2(h[2 * j + 1], xk2, w.y);
        }
    }
    u64* pap = (u64*)&g_pa[(long)idx * 64];
    #pragma unroll
    for (int j = 0; j < 32; j++) pap[j] = h[j];

    #pragma unroll
    for (int j = 0; j < 32; j++) h[j] = 0ull;
    #pragma unroll
    for (int k = 0; k < 32; k++) {
        const u64 xk2 = pack2s(xf[k]);
        const ulonglong2* wr = (const ulonglong2*)&s_w[(32 + k) * 64];
        #pragma unroll
        for (int j = 0; j < 16; j++) {
            ulonglong2 w = wr[j];
            fma2(h[2 * j], xk2, w.x);
            fma2(h[2 * j + 1], xk2, w.y);
        }
    }
    u64* pbp = (u64*)&g_pb[(long)idx * 64];
    #pragma unroll
    for (int j = 0; j < 32; j++) pbp[j] = h[j];
}

// ---------------- bond kernel: warp-uniform-weight tiling ----------------
// block = 128 bonds, 128 threads (4 warps). Every warp processes ALL 128 bonds.
// Warp w owns outputs [16w,16w+16) in layers 1-2 and [8w,8w+8) in layer 3.
// Thread = 4 consecutive bonds (chunk = lane) x warp's outputs.
// sX: [row][bond], XOR-swizzled 16B chunks: phys = chunk ^ ((row>>3)&7).
__global__ void __launch_bounds__(128, 4) bond_kernel(
    const float* __restrict__ bonds, const int* __restrict__ ba1,
    const int* __restrict__ ba2,
    const float* __restrict__ w1, const float* __restrict__ w2,
    const float* __restrict__ b2v, const float* __restrict__ w3,
    const float* __restrict__ b3v, float* __restrict__ out_bonds)
{
    __shared__ __align__(16) float sX[64 * 128];   // 32 KB

    const int tid = threadIdx.x;
    const int w = tid >> 5;
    const int lane = tid & 31;
    const int j0 = w * 16;             // layers 1-2 output base (warp-uniform)
    const long row0 = (long)blockIdx.x * 128;
    const int b = blockIdx.x >> 11;    // 2048 blocks per batch

    // stage bond features (thread tid stages bond tid), swizzled
    {
        const float4* p = (const float4*)(bonds + (row0 + tid) * FF);
        const int cch = tid >> 2, cw = tid & 3;
        #pragma unroll
        for (int q = 0; q < 8; q++) {
            float4 v = __ldg(&p[q]);
            float vv[4] = {v.x, v.y, v.z, v.w};
            #pragma unroll
            for (int r = 0; r < 4; r++) {
                int k = 4 * q + r;
                sX[k * 128 + (((cch ^ ((k >> 3) & 7)) << 2) | cw)] = vv[r];
            }
        }
    }
    __syncthreads();

    u64 acc[4][8];
    #pragma unroll
    for (int s = 0; s < 4; s++)
        #pragma unroll
        for (int p = 0; p < 8; p++) acc[s][p] = 0ull;

    // ---- layer 1: K=32, weights = W1 rows 64..95, warp-uniform LDG ----
    #pragma unroll 8
    for (int k = 0; k < 32; k++) {
        const int K = (k >> 3) & 7;
        const float4 x = *(const float4*)&sX[k * 128 + ((lane ^ K) << 2)];
        const float* wrow = w1 + (64 + k) * 64 + j0;
        ulonglong2 q0 = __ldg((const ulonglong2*)wrow);
        ulonglong2 q1 = __ldg((const ulonglong2*)(wrow + 4));
        ulonglong2 q2 = __ldg((const ulonglong2*)(wrow + 8));
        ulonglong2 q3 = __ldg((const ulonglong2*)(wrow + 12));
        const u64 wr[8] = {q0.x, q0.y, q1.x, q1.y, q2.x, q2.y, q3.x, q3.y};
        const float xs[4] = {x.x, x.y, x.z, x.w};
        #pragma unroll
        for (int s = 0; s < 4; s++) {
            const u64 x2 = pack2s(xs[s]);
            #pragma unroll
            for (int p = 0; p < 8; p++) fma2(acc[s][p], x2, wr[p]);
        }
    }
    __syncthreads();

    // ---- epilogue 1: + pa[a1] + pb[a2] (my 16-out slice), softplus ----
    #pragma unroll
    for (int s = 0; s < 4; s++) {
        const int c = 4 * lane + s;
        const long row = row0 + c;
        const int a1 = __ldg(&ba1[row]);
        const int a2 = __ldg(&ba2[row]);
        const float* pap = g_pa + ((long)b * NATM + a1) * 64 + j0;
        const float* pbp = g_pb + ((long)b * NATM + a2) * 64 + j0;
        float4 A[4], Bq[4];
        #pragma unroll
        for (int g = 0; g < 4; g++) {
            A[g] = __ldg((const float4*)(pap + 4 * g));
            Bq[g] = __ldg((const float4*)(pbp + 4 * g));
        }
        const float* Af = (const float*)A;
        const float* Bf = (const float*)Bq;
        #pragma unroll
        for (int p = 0; p < 8; p++) {
            float v0, v1;
            unpack2(acc[s][p], v0, v1);
            acc[s][p] = pack2(softplus(v0 + Af[2 * p] + Bf[2 * p]),
                              softplus(v1 + Af[2 * p + 1] + Bf[2 * p + 1]));
        }
    }
    // transposed store: 16 rows, 1 STS.128 per row (4 bonds)
    #pragma unroll
    for (int jr = 0; jr < 16; jr++) {
        const int r = j0 + jr;
        const int S = (r >> 3) & 7;
        const int p = jr >> 1;
        float t0, t1, t2, t3, lo, hi;
        unpack2(acc[0][p], lo, hi); t0 = (jr & 1) ? hi : lo;
        unpack2(acc[1][p], lo, hi); t1 = (jr & 1) ? hi : lo;
        unpack2(acc[2][p], lo, hi); t2 = (jr & 1) ? hi : lo;
        unpack2(acc[3][p], lo, hi); t3 = (jr & 1) ? hi : lo;
        *(float4*)&sX[r * 128 + ((lane ^ S) << 2)] = make_float4(t0, t1, t2, t3);
    }
    __syncthreads();

    // ---- layer 2: K=64, W2 warp-uniform LDG ----
    #pragma unroll
    for (int s = 0; s < 4; s++)
        #pragma unroll
        for (int p = 0; p < 8; p++) acc[s][p] = 0ull;
    #pragma unroll 8
    for (int k = 0; k < 64; k++) {
        const int K = (k >> 3) & 7;
        const float4 x = *(const float4*)&sX[k * 128 + ((lane ^ K) << 2)];
        const float* wrow = w2 + k * 64 + j0;
        ulonglong2 q0 = __ldg((const ulonglong2*)wrow);
        ulonglong2 q1 = __ldg((const ulonglong2*)(wrow + 4));
        ulonglong2 q2 = __ldg((const ulonglong2*)(wrow + 8));
        ulonglong2 q3 = __ldg((const ulonglong2*)(wrow + 12));
        const u64 wr[8] = {q0.x, q0.y, q1.x, q1.y, q2.x, q2.y, q3.x, q3.y};
        const float xs[4] = {x.x, x.y, x.z, x.w};
        #pragma unroll
        for (int s = 0; s < 4; s++) {
            const u64 x2 = pack2s(xs[s]);
            #pragma unroll
            for (int p = 0; p < 8; p++) fma2(acc[s][p], x2, wr[p]);
        }
    }
    __syncthreads();

    // ---- epilogue 2: + b2 (warp-uniform), softplus, transposed store ----
    {
        float4 bq[4];
        #pragma unroll
        for (int g = 0; g < 4; g++) bq[g] = __ldg((const float4*)(b2v + j0 + 4 * g));
        const float* bb = (const float*)bq;
        #pragma unroll
        for (int s = 0; s < 4; s++) {
            #pragma unroll
            for (int p = 0; p < 8; p++) {
                float v0, v1;
                unpack2(acc[s][p], v0, v1);
                acc[s][p] = pack2(softplus(v0 + bb[2 * p]), softplus(v1 + bb[2 * p + 1]));
            }
        }
        #pragma unroll
        for (int jr = 0; jr < 16; jr++) {
            const int r = j0 + jr;
            const int S = (r >> 3) & 7;
            const int p = jr >> 1;
            float t0, t1, t2, t3, lo, hi;
            unpack2(acc[0][p], lo, hi); t0 = (jr & 1) ? hi : lo;
            unpack2(acc[1][p], lo, hi); t1 = (jr & 1) ? hi : lo;
            unpack2(acc[2][p], lo, hi); t2 = (jr & 1) ? hi : lo;
            unpack2(acc[3][p], lo, hi); t3 = (jr & 1) ? hi : lo;
            *(float4*)&sX[r * 128 + ((lane ^ S) << 2)] = make_float4(t0, t1, t2, t3);
        }
    }
    __syncthreads();

    // ---- layer 3: K=64, N=32; warp owns outputs [8w, 8w+8) ----
    const int j0b = w * 8;
    u64 a3[4][4];
    #pragma unroll
    for (int s = 0; s < 4; s++)
        #pragma unroll
        for (int q = 0; q < 4; q++) a3[s][q] = 0ull;
    #pragma unroll 8
    for (int k = 0; k < 64; k++) {
        const int K = (k >> 3) & 7;
        const float4 x = *(const float4*)&sX[k * 128 + ((lane ^ K) << 2)];
        const float* wrow = w3 + k * 32 + j0b;
        ulonglong2 q0 = __ldg((const ulonglong2*)wrow);
        ulonglong2 q1 = __ldg((const ulonglong2*)(wrow + 4));
        const u64 wr[4] = {q0.x, q0.y, q1.x, q1.y};
        const float xs[4] = {x.x, x.y, x.z, x.w};
        #pragma unroll
        for (int s = 0; s < 4; s++) {
            const u64 x2 = pack2s(xs[s]);
            #pragma unroll
            for (int q = 0; q < 4; q++) fma2(a3[s][q], x2, wr[q]);
        }
    }

    // ---- epilogue 3: + b3, softplus, STG (my 8-out slice) + red scatter ----
    {
        float4 bq0 = __ldg((const float4*)(b3v + j0b));
        float4 bq1 = __ldg((const float4*)(b3v + j0b + 4));
        #pragma unroll
        for (int s = 0; s < 4; s++) {
            const int c = 4 * lane + s;
            const long row = row0 + c;
            const int a1 = __ldg(&ba1[row]);
            float o0, o1, o2, o3, o4, o5, o6, o7;
            unpack2(a3[s][0], o0, o1);
            unpack2(a3[s][1], o2, o3);
            unpack2(a3[s][2], o4, o5);
            unpack2(a3[s][3], o6, o7);
            o0 = softplus(o0 + bq0.x); o1 = softplus(o1 + bq0.y);
            o2 = softplus(o2 + bq0.z); o3 = softplus(o3 + bq0.w);
            o4 = softplus(o4 + bq1.x); o5 = softplus(o5 + bq1.y);
            o6 = softplus(o6 + bq1.z); o7 = softplus(o7 + bq1.w);
            float* orow = out_bonds + row * FF + j0b;
            *(float4*)orow = make_float4(o0, o1, o2, o3);
            *(float4*)(orow + 4) = make_float4(o4, o5, o6, o7);
            float* dst = g_bta + ((long)b * NATM + a1) * FF + j0b;
            red4(dst, o0, o1, o2, o3);
            red4(dst + 4, o4, o5, o6, o7);
            if (w == 0) atomicAdd(&g_cnt[b * NATM + a1], 1.0f);
        }
    }
}

__device__ __forceinline__ float warp_reduce_rows(const float* v, int lane) {
    float part = 0.0f;
    #pragma unroll
    for (int j = 0; j < 32; j++) {
        float x = v[j];
        x += __shfl_xor_sync(0xffffffffu, x, 16);
        x += __shfl_xor_sync(0xffffffffu, x, 8);
        x += __shfl_xor_sync(0xffffffffu, x, 4);
        x += __shfl_xor_sync(0xffffffffu, x, 2);
        x += __shfl_xor_sync(0xffffffffu, x, 1);
        if (lane == j) part = x;
    }
    return part;
}

// ---------------- atom kernel (unchanged, proven) ----------------
__global__ void __launch_bounds__(128, 1) atom_kernel(
    const float* __restrict__ atoms, const float* __restrict__ state,
    const float* __restrict__ w1, const float* __restrict__ b1,
    const float* __restrict__ w2, const float* __restrict__ b2,
    const float* __restrict__ w3, const float* __restrict__ b3,
    float* __restrict__ out_atoms)
{
    __shared__ __align__(16) float s_w1[96 * 64];
    __shared__ __align__(16) float s_w2[64 * 64];
    __shared__ __align__(16) float s_hst[64];
    __shared__ float s_red[2][4][32];

    const int tid = threadIdx.x;
    const int lane = tid & 31;
    const int warp = tid >> 5;
    for (int i = tid; i < 96 * 64; i += 128) s_w1[i] = w1[i];
    for (int i = tid; i < 64 * 64; i += 128) s_w2[i] = w2[i];
    __syncthreads();

    const long row0 = (long)blockIdx.x * 128;
    const int b = (int)(row0 / NATM);

    if (tid < 64) {
        float acc = __ldg(&b1[tid]);
        const float* st = state + b * FF;
        #pragma unroll
        for (int k = 0; k < 32; k++) acc = fmaf(st[k], s_w1[(64 + k) * 64 + tid], acc);
        s_hst[tid] = acc;
    }
    __syncthreads();

    const long row = row0 + tid;
    const int a = (int)(row - (long)b * NATM);

    float x0[32];
    const float* braw = &g_bta[((long)b * NATM + a) * FF];
    #pragma unroll
    for (int k = 0; k < 32; k++) x0[k] = braw[k];
    s_red[0][warp][lane] = warp_reduce_rows(x0, lane);

    const float invc = 1.0f / g_cnt[b * NATM + a];

    u64 h[32];
    {
        const u64* hs = (const u64*)s_hst;
        #pragma unroll
        for (int j = 0; j < 32; j++) h[j] = hs[j];
    }
    #pragma unroll
    for (int k = 0; k < 32; k++) {
        const u64 xk2 = pack2s(x0[k] * invc);
        const ulonglong2* wr = (const ulonglong2*)&s_w1[k * 64];
        #pragma unroll
        for (int j = 0; j < 16; j++) {
            ulonglong2 w = wr[j];
            fma2(h[2 * j], xk2, w.x);
            fma2(h[2 * j + 1], xk2, w.y);
        }
    }
    {
        const float4* p = (const float4*)(atoms + ((long)b * NATM + a) * FF);
        float4 xv[8];
        #pragma unroll
        for (int q = 0; q < 8; q++) xv[q] = __ldg(&p[q]);
        const float* xf = (const float*)xv;
        #pragma unroll
        for (int k = 0; k < 32; k++) {
            const u64 xk2 = pack2s(xf[k]);
            const ulonglong2* wr = (const ulonglong2*)&s_w1[(32 + k) * 64];
            #pragma unroll
            for (int j = 0; j < 16; j++) {
                ulonglong2 w = wr[j];
                fma2(h[2 * j], xk2, w.x);
                fma2(h[2 * j + 1], xk2, w.y);
            }
        }
    }

    __syncthreads();
    for (int t = tid; t < 64 * 32; t += 128) s_w1[t] = w3[t];

    u64 h2[32];
    {
        const u64* bp = (const u64*)b2;
        #pragma unroll
        for (int j = 0; j < 32; j++) h2[j] = __ldg(&bp[j]);
    }
    #pragma unroll
    for (int kp = 0; kp < 32; kp++) {
        float xa, xb;
        unpack2(h[kp], xa, xb);
        const u64 xa2 = pack2s(softplus(xa));
        const u64 xb2 = pack2s(softplus(xb));
        const ulonglong2* wa = (const ulonglong2*)&s_w2[(2 * kp) * 64];
        const ulonglong2* wb = (const ulonglong2*)&s_w2[(2 * kp + 1) * 64];
        #pragma unroll
        for (int j = 0; j < 16; j++) {
            ulonglong2 w = wa[j];
            fma2(h2[2 * j], xa2, w.x);
            fma2(h2[2 * j + 1], xa2, w.y);
        }
        #pragma unroll
        for (int j = 0; j < 16; j++) {
            ulonglong2 w = wb[j];
            fma2(h2[2 * j], xb2, w.x);
            fma2(h2[2 * j + 1], xb2, w.y);
        }
    }

    __syncthreads();

    u64 o[16];
    {
        const u64* bp = (const u64*)b3;
        #pragma unroll
        for (int j = 0; j < 16; j++) o[j] = __ldg(&bp[j]);
    }
    #pragma unroll
    for (int kp = 0; kp < 32; kp++) {
        float xa, xb;
        unpack2(h2[kp], xa, xb);
        const u64 xa2 = pack2s(softplus(xa));
        const u64 xb2 = pack2s(softplus(xb));
        const ulonglong2* wa = (const ulonglong2*)&s_w1[(2 * kp) * 32];
        const ulonglong2* wb = (const ulonglong2*)&s_w1[(2 * kp + 1) * 32];
        #pragma unroll
        for (int j = 0; j < 8; j++) {
            ulonglong2 w = wa[j];
            fma2(o[2 * j], xa2, w.x);
            fma2(o[2 * j + 1], xa2, w.y);
        }
        #pragma unroll
        for (int j = 0; j < 8; j++) {
            ulonglong2 w = wb[j];
            fma2(o[2 * j], xb2, w.x);
            fma2(o[2 * j + 1], xb2, w.y);
        }
    }

    float of[32];
    #pragma unroll
    for (int j = 0; j < 16; j++) {
        float xa, xb;
        unpack2(o[j], xa, xb);
        of[2 * j] = softplus(xa);
        of[2 * j + 1] = softplus(xb);
    }

    float* orow = out_atoms + row * FF;
    #pragma unroll
    for (int q = 0; q < 8; q++)
        ((float4*)orow)[q] = make_float4(of[q * 4], of[q * 4 + 1], of[q * 4 + 2], of[q * 4 + 3]);

    s_red[1][warp][lane] = warp_reduce_rows(of, lane);
    __syncthreads();
    if (warp == 0) {
        float bs = s_red[0][0][lane] + s_red[0][1][lane] + s_red[0][2][lane] + s_red[0][3][lane];
        float as = s_red[1][0][lane] + s_red[1][1][lane] + s_red[1][2][lane] + s_red[1][3][lane];
        atomicAdd(&g_bond_sum[b * FF + lane], bs);
        atomicAdd(&g_atom_sum[b * FF + lane], as);
    }
}

// ---------------- state kernel ----------------
__global__ void __launch_bounds__(64) state_kernel(
    const float* __restrict__ state,
    const float* __restrict__ w1, const float* __restrict__ b1,
    const float* __restrict__ w2, const float* __restrict__ b2,
    const float* __restrict__ w3, const float* __restrict__ b3,
    float* __restrict__ out_state)
{
    __shared__ float u_in[96];
    __shared__ float h1s[64];
    __shared__ float h2s[64];
    const int b = blockIdx.x;
    const int t = threadIdx.x;
    if (t < 32) {
        u_in[t]      = g_bond_sum[b * FF + t] * (1.0f / NBND);
        u_in[32 + t] = g_atom_sum[b * FF + t] * (1.0f / NATM);
        u_in[64 + t] = state[b * FF + t];
    }
    __syncthreads();
    {
        float acc = __ldg(&b1[t]);
        for (int k = 0; k < 96; k++) acc = fmaf(u_in[k], __ldg(&w1[k * 64 + t]), acc);
        h1s[t] = softplus(acc);
    }
    __syncthreads();
    {
        float acc = __ldg(&b2[t]);
        for (int k = 0; k < 64; k++) acc = fmaf(h1s[k], __ldg(&w2[k * 64 + t]), acc);
        h2s[t] = softplus(acc);
    }
    __syncthreads();
    if (t < 32) {
        float acc = __ldg(&b3[t]);
        for (int k = 0; k < 64; k++) acc = fmaf(h2s[k], __ldg(&w3[k * 32 + t]), acc);
        out_state[b * FF + t] = softplus(acc);
    }
}

extern "C" void kernel_launch(void* const* d_in, const int* in_sizes, int n_in,
                              void* d_out, int out_size)
{
    const float* bonds = (const float*)d_in[0];
    const int*   ba1   = (const int*)d_in[1];
    const int*   ba2   = (const int*)d_in[2];
    const float* atoms = (const float*)d_in[3];
    const float* state = (const float*)d_in[4];
    const float* ew1 = (const float*)d_in[5];
    const float* eb1 = (const float*)d_in[6];
    const float* ew2 = (const float*)d_in[7];
    const float* eb2 = (const float*)d_in[8];
    const float* ew3 = (const float*)d_in[9];
    const float* eb3 = (const float*)d_in[10];
    const float* vw1 = (const float*)d_in[11];
    const float* vb1 = (const float*)d_in[12];
    const float* vw2 = (const float*)d_in[13];
    const float* vb2 = (const float*)d_in[14];
    const float* vw3 = (const float*)d_in[15];
    const float* vb3 = (const float*)d_in[16];
    const float* uw1 = (const float*)d_in[17];
    const float* ub1 = (const float*)d_in[18];
    const float* uw2 = (const float*)d_in[19];
    const float* ub2 = (const float*)d_in[20];
    const float* uw3 = (const float*)d_in[21];
    const float* ub3 = (const float*)d_in[22];

    float* out = (float*)d_out;
    float* out_bonds = out;
    float* out_atoms = out + (long)BB * NBND * FF;
    float* out_state = out_atoms + (long)BB * NATM * FF;

    zero_kernel<<<(BB * NATM * FF + 255) / 256, 256>>>();
    atom_pre_kernel<<<(BB * NATM) / 128, 128>>>(atoms, ew1, eb1, state);
    bond_kernel<<<(BB * NBND) / 128, 128>>>(bonds, ba1, ba2,
                                            ew1, ew2, eb2, ew3, eb3, out_bonds);
    atom_kernel<<<(BB * NATM) / 128, 128>>>(atoms, state,
                                            vw1, vb1, vw2, vb2, vw3, vb3, out_atoms);
    state_kernel<<<BB, 64>>>(state, uw1, ub1, uw2, ub2, uw3, ub3, out_state);
}

// round 12
// speedup vs baseline: 1.4113x; 1.4113x over previous
#include <cuda_runtime.h>
#include <cuda_bf16.h>

#define BB 4
#define NBND 262144
#define NATM 8192
#define FF 32

typedef unsigned long long u64;

__device__ float g_bta[BB * NATM * FF];
__device__ float g_cnt[BB * NATM];
__device__ float g_bond_sum[BB * FF];
__device__ float g_atom_sum[BB * FF];
__device__ __align__(16) float g_pa[BB * NATM * 64];  // hst + atoms@W1[0:32]
__device__ __align__(16) float g_pb[BB * NATM * 64];  // atoms@W1[32:64]

__device__ __forceinline__ float softplus(float x) {
    return fmaxf(x, 0.0f) + __logf(1.0f + __expf(-fabsf(x)));
}
__device__ __forceinline__ u64 pack2(float lo, float hi) {
    u64 r; asm("mov.b64 %0, {%1, %2};" : "=l"(r) : "f"(lo), "f"(hi)); return r;
}
__device__ __forceinline__ u64 pack2s(float x) { return pack2(x, x); }
__device__ __forceinline__ void unpack2(u64 v, float& lo, float& hi) {
    asm("mov.b64 {%0, %1}, %2;" : "=f"(lo), "=f"(hi) : "l"(v));
}
__device__ __forceinline__ void fma2(u64& d, u64 a, u64 b) {
    asm("fma.rn.f32x2 %0, %1, %2, %0;" : "+l"(d) : "l"(a), "l"(b));
}
__device__ __forceinline__ void red4(float* p, float a, float b, float c, float d) {
    asm volatile("red.global.add.v4.f32 [%0], {%1, %2, %3, %4};"
                 :: "l"(p), "f"(a), "f"(b), "f"(c), "f"(d) : "memory");
}

__global__ void zero_kernel() {
    long i = (long)blockIdx.x * 256 + threadIdx.x;
    if (i < (long)BB * NATM * FF) g_bta[i] = 0.0f;
    if (i < BB * NATM) g_cnt[i] = 0.0f;
    if (i < BB * FF) { g_bond_sum[i] = 0.0f; g_atom_sum[i] = 0.0f; }
}

// per-atom projections pa/pb (1 thread = 1 atom); hst computed in-block
__global__ void __launch_bounds__(128) atom_pre_kernel(
    const float* __restrict__ atoms, const float* __restrict__ w1,
    const float* __restrict__ b1, const float* __restrict__ state)
{
    __shared__ __align__(16) float s_w[64 * 64];
    __shared__ __align__(16) float s_hst[64];
    const int tid = threadIdx.x;
    const int idx = blockIdx.x * 128 + tid;
    const int b = idx / NATM;
    for (int i = tid; i < 64 * 64; i += 128) s_w[i] = w1[i];
    if (tid < 64) {
        float acc = __ldg(&b1[tid]);
        #pragma unroll
        for (int k = 0; k < 32; k++)
            acc = fmaf(__ldg(&state[b * FF + k]), __ldg(&w1[(96 + k) * 64 + tid]), acc);
        s_hst[tid] = acc;
    }
    __syncthreads();

    float4 xv[8];
    const float4* p = (const float4*)(atoms + (long)idx * FF);
    #pragma unroll
    for (int q = 0; q < 8; q++) xv[q] = __ldg(&p[q]);
    const float* xf = (const float*)xv;

    u64 h[32];
    const u64* hstp = (const u64*)s_hst;
    #pragma unroll
    for (int j = 0; j < 32; j++) h[j] = hstp[j];
    #pragma unroll
    for (int k = 0; k < 32; k++) {
        const u64 xk2 = pack2s(xf[k]);
        const ulonglong2* wr = (const ulonglong2*)&s_w[k * 64];
        #pragma unroll
        for (int j = 0; j < 16; j++) {
            ulonglong2 w = wr[j];
            fma2(h[2 * j], xk2, w.x);
            fma2(h[2 * j + 1], xk2, w.y);
        }
    }
    u64* pap = (u64*)&g_pa[(long)idx * 64];
    #pragma unroll
    for (int j = 0; j < 32; j++) pap[j] = h[j];

    #pragma unroll
    for (int j = 0; j < 32; j++) h[j] = 0ull;
    #pragma unroll
    for (int k = 0; k < 32; k++) {
        const u64 xk2 = pack2s(xf[k]);
        const ulonglong2* wr = (const ulonglong2*)&s_w[(32 + k) * 64];
        #pragma unroll
        for (int j = 0; j < 16; j++) {
            ulonglong2 w = wr[j];
            fma2(h[2 * j], xk2, w.x);
            fma2(h[2 * j + 1], xk2, w.y);
        }
    }
    u64* pbp = (u64*)&g_pb[(long)idx * 64];
    #pragma unroll
    for (int j = 0; j < 32; j++) pbp[j] = h[j];
}

// ---------------- bond kernel: round-10 proven version (429 us) ----------------
__global__ void __launch_bounds__(128, 4) bond_kernel(
    const float* __restrict__ bonds, const int* __restrict__ ba1,
    const int* __restrict__ ba2,
    const float* __restrict__ w1, const float* __restrict__ w2,
    const float* __restrict__ b2v, const float* __restrict__ w3,
    const float* __restrict__ b3v, float* __restrict__ out_bonds)
{
    __shared__ __align__(16) float sW2[64 * 64];
    __shared__ __align__(16) float sX[64 * 128];

    const int tid = threadIdx.x;
    const int w = tid >> 5;
    const int lane = tid & 31;
    const int ti = lane & 3;
    const int tj = lane >> 2;
    const int j0 = tj * 8;
    const int c0 = w * 32 + ti * 8;
    const int ch0 = c0 >> 2;
    const long row0 = (long)blockIdx.x * 128;
    const int b = blockIdx.x >> 11;

    for (int i = tid; i < 1024; i += 128)
        ((float4*)sW2)[i] = __ldg(&((const float4*)w2)[i]);

    {
        const float4* p = (const float4*)(bonds + (row0 + tid) * FF);
        const int cch = tid >> 2, cw = tid & 3;
        #pragma unroll
        for (int q = 0; q < 8; q++) {
            float4 v = __ldg(&p[q]);
            float vv[4] = {v.x, v.y, v.z, v.w};
            #pragma unroll
            for (int r = 0; r < 4; r++) {
                int k = 4 * q + r;
                sX[k * 128 + (((cch ^ ((k >> 3) & 7)) << 2) | cw)] = vv[r];
            }
        }
    }
    __syncthreads();

    u64 acc[8][4];
    #pragma unroll
    for (int s = 0; s < 8; s++)
        #pragma unroll
        for (int jp = 0; jp < 4; jp++) acc[s][jp] = 0ull;

    #pragma unroll 4
    for (int k = 0; k < 32; k++) {
        const int K = (k >> 3) & 7;
        const float4 x0 = *(const float4*)&sX[k * 128 + ((ch0 ^ K) << 2)];
        const float4 x1 = *(const float4*)&sX[k * 128 + (((ch0 + 1) ^ K) << 2)];
        const ulonglong2 wA = __ldg((const ulonglong2*)(w1 + (64 + k) * 64 + j0));
        const ulonglong2 wB = __ldg((const ulonglong2*)(w1 + (64 + k) * 64 + j0 + 4));
        const float xs[8] = {x0.x, x0.y, x0.z, x0.w, x1.x, x1.y, x1.z, x1.w};
        #pragma unroll
        for (int s = 0; s < 8; s++) {
            const u64 x2 = pack2s(xs[s]);
            fma2(acc[s][0], x2, wA.x);
            fma2(acc[s][1], x2, wA.y);
            fma2(acc[s][2], x2, wB.x);
            fma2(acc[s][3], x2, wB.y);
        }
    }
    __syncthreads();

    #pragma unroll
    for (int s = 0; s < 8; s++) {
        const long row = row0 + c0 + s;
        const int a1 = __ldg(&ba1[row]);
        const int a2 = __ldg(&ba2[row]);
        const float* pap = g_pa + ((long)b * NATM + a1) * 64 + j0;
        const float* pbp = g_pb + ((long)b * NATM + a2) * 64 + j0;
        float4 A0 = __ldg((const float4*)pap), A1 = __ldg((const float4*)(pap + 4));
        float4 B0 = __ldg((const float4*)pbp), B1 = __ldg((const float4*)(pbp + 4));
        float v0, v1;
        unpack2(acc[s][0], v0, v1);
        acc[s][0] = pack2(softplus(v0 + A0.x + B0.x), softplus(v1 + A0.y + B0.y));
        unpack2(acc[s][1], v0, v1);
        acc[s][1] = pack2(softplus(v0 + A0.z + B0.z), softplus(v1 + A0.w + B0.w));
        unpack2(acc[s][2], v0, v1);
        acc[s][2] = pack2(softplus(v0 + A1.x + B1.x), softplus(v1 + A1.y + B1.y));
        unpack2(acc[s][3], v0, v1);
        acc[s][3] = pack2(softplus(v0 + A1.z + B1.z), softplus(v1 + A1.w + B1.w));
    }
    #pragma unroll
    for (int jj = 0; jj < 8; jj++) {
        const int r = j0 + jj;
        const int S = (r >> 3) & 7;
        const int jp = jj >> 1;
        float t0, t1, t2, t3, t4, t5, t6, t7, lo, hi;
        unpack2(acc[0][jp], lo, hi); t0 = (jj & 1) ? hi : lo;
        unpack2(acc[1][jp], lo, hi); t1 = (jj & 1) ? hi : lo;
        unpack2(acc[2][jp], lo, hi); t2 = (jj & 1) ? hi : lo;
        unpack2(acc[3][jp], lo, hi); t3 = (jj & 1) ? hi : lo;
        unpack2(acc[4][jp], lo, hi); t4 = (jj & 1) ? hi : lo;
        unpack2(acc[5][jp], lo, hi); t5 = (jj & 1) ? hi : lo;
        unpack2(acc[6][jp], lo, hi); t6 = (jj & 1) ? hi : lo;
        unpack2(acc[7][jp], lo, hi); t7 = (jj & 1) ? hi : lo;
        *(float4*)&sX[r * 128 + ((ch0 ^ S) << 2)] = make_float4(t0, t1, t2, t3);
        *(float4*)&sX[r * 128 + (((ch0 + 1) ^ S) << 2)] = make_float4(t4, t5, t6, t7);
    }
    __syncthreads();

    #pragma unroll
    for (int s = 0; s < 8; s++)
        #pragma unroll
        for (int jp = 0; jp < 4; jp++) acc[s][jp] = 0ull;
    for (int kk = 0; kk < 64; kk += 8) {
        const int K = kk >> 3;
        const float* xr = &sX[kk * 128];
        const float* wr = &sW2[kk * 64];
        #pragma unroll
        for (int u = 0; u < 8; u++) {
            const float4 x0 = *(const float4*)&xr[u * 128 + ((ch0 ^ K) << 2)];
            const float4 x1 = *(const float4*)&xr[u * 128 + (((ch0 + 1) ^ K) << 2)];
            const ulonglong2 wA = *(const ulonglong2*)&wr[u * 64 + j0];
            const ulonglong2 wB = *(const ulonglong2*)&wr[u * 64 + j0 + 4];
            const float xs[8] = {x0.x, x0.y, x0.z, x0.w, x1.x, x1.y, x1.z, x1.w};
            #pragma unroll
            for (int s = 0; s < 8; s++) {
                const u64 x2 = pack2s(xs[s]);
                fma2(acc[s][0], x2, wA.x);
                fma2(acc[s][1], x2, wA.y);
                fma2(acc[s][2], x2, wB.x);
                fma2(acc[s][3], x2, wB.y);
            }
        }
    }
    __syncthreads();

    {
        float4 bA = __ldg((const float4*)(b2v + j0));
        float4 bB = __ldg((const float4*)(b2v + j0 + 4));
        #pragma unroll
        for (int s = 0; s < 8; s++) {
            float v0, v1;
            unpack2(acc[s][0], v0, v1);
            acc[s][0] = pack2(softplus(v0 + bA.x), softplus(v1 + bA.y));
            unpack2(acc[s][1], v0, v1);
            acc[s][1] = pack2(softplus(v0 + bA.z), softplus(v1 + bA.w));
            unpack2(acc[s][2], v0, v1);
            acc[s][2] = pack2(softplus(v0 + bB.x), softplus(v1 + bB.y));
            unpack2(acc[s][3], v0, v1);
            acc[s][3] = pack2(softplus(v0 + bB.z), softplus(v1 + bB.w));
        }
        #pragma unroll
        for (int jj = 0; jj < 8; jj++) {
            const int r = j0 + jj;
            const int S = (r >> 3) & 7;
            const int jp = jj >> 1;
            float t0, t1, t2, t3, t4, t5, t6, t7, lo, hi;
            unpack2(acc[0][jp], lo, hi); t0 = (jj & 1) ? hi : lo;
            unpack2(acc[1][jp], lo, hi); t1 = (jj & 1) ? hi : lo;
            unpack2(acc[2][jp], lo, hi); t2 = (jj & 1) ? hi : lo;
            unpack2(acc[3][jp], lo, hi); t3 = (jj & 1) ? hi : lo;
            unpack2(acc[4][jp], lo, hi); t4 = (jj & 1) ? hi : lo;
            unpack2(acc[5][jp], lo, hi); t5 = (jj & 1) ? hi : lo;
            unpack2(acc[6][jp], lo, hi); t6 = (jj & 1) ? hi : lo;
            unpack2(acc[7][jp], lo, hi); t7 = (jj & 1) ? hi : lo;
            *(float4*)&sX[r * 128 + ((ch0 ^ S) << 2)] = make_float4(t0, t1, t2, t3);
            *(float4*)&sX[r * 128 + (((ch0 + 1) ^ S) << 2)] = make_float4(t4, t5, t6, t7);
        }
    }
    __syncthreads();

    const int j0b = tj * 4;
    u64 a3[8][2];
    #pragma unroll
    for (int s = 0; s < 8; s++) { a3[s][0] = 0ull; a3[s][1] = 0ull; }
    for (int kk = 0; kk < 64; kk += 8) {
        const int K = kk >> 3;
        const float* xr = &sX[kk * 128];
        #pragma unroll
        for (int u = 0; u < 8; u++) {
            const float4 x0 = *(const float4*)&xr[u * 128 + ((ch0 ^ K) << 2)];
            const float4 x1 = *(const float4*)&xr[u * 128 + (((ch0 + 1) ^ K) << 2)];
            const ulonglong2 wv = __ldg((const ulonglong2*)(w3 + (kk + u) * 32 + j0b));
            const float xs[8] = {x0.x, x0.y, x0.z, x0.w, x1.x, x1.y, x1.z, x1.w};
            #pragma unroll
            for (int s = 0; s < 8; s++) {
                const u64 x2 = pack2s(xs[s]);
                fma2(a3[s][0], x2, wv.x);
                fma2(a3[s][1], x2, wv.y);
            }
        }
    }

    {
        float4 b3q = __ldg((const float4*)(b3v + j0b));
        #pragma unroll
        for (int s = 0; s < 8; s++) {
            const long row = row0 + c0 + s;
            const int a1 = __ldg(&ba1[row]);
            float o0, o1, o2, o3;
            unpack2(a3[s][0], o0, o1);
            unpack2(a3[s][1], o2, o3);
            o0 = softplus(o0 + b3q.x);
            o1 = softplus(o1 + b3q.y);
            o2 = softplus(o2 + b3q.z);
            o3 = softplus(o3 + b3q.w);
            *(float4*)(out_bonds + row * FF + j0b) = make_float4(o0, o1, o2, o3);
            red4(g_bta + ((long)b * NATM + a1) * FF + j0b, o0, o1, o2, o3);
            if (tj == 0) atomicAdd(&g_cnt[b * NATM + a1], 1.0f);
        }
    }
}

// ---------------- atom main kernel: v-MLP, warp-tiled like bond kernel ----------------
// block = 128 atoms; warp = 32 atoms x 64 outs; thread = 8 atoms x 8 outs.
// sX rows 0..31 = bta*invc, rows 32..63 = atom features.
__global__ void __launch_bounds__(128, 4) atom_main_kernel(
    const float* __restrict__ atoms, const float* __restrict__ state,
    const float* __restrict__ w1, const float* __restrict__ b1,
    const float* __restrict__ w2, const float* __restrict__ b2v,
    const float* __restrict__ w3, const float* __restrict__ b3v,
    float* __restrict__ out_atoms)
{
    __shared__ __align__(16) float sW2[64 * 64];
    __shared__ __align__(16) float sX[64 * 128];
    __shared__ __align__(16) float s_hst[64];

    const int tid = threadIdx.x;
    const int w = tid >> 5;
    const int lane = tid & 31;
    const int ti = lane & 3;
    const int tj = lane >> 2;
    const int j0 = tj * 8;
    const int c0 = w * 32 + ti * 8;
    const int ch0 = c0 >> 2;
    const long row0 = (long)blockIdx.x * 128;
    const int b = blockIdx.x >> 6;      // 64 blocks per batch

    for (int i = tid; i < 1024; i += 128)
        ((float4*)sW2)[i] = __ldg(&((const float4*)w2)[i]);

    if (tid < 64) {
        float acc = __ldg(&b1[tid]);
        #pragma unroll
        for (int k = 0; k < 32; k++)
            acc = fmaf(__ldg(&state[b * FF + k]), __ldg(&w1[(64 + k) * 64 + tid]), acc);
        s_hst[tid] = acc;
    }

    // stage inputs: rows 0..31 = g_bta*invc, rows 32..63 = atoms
    {
        const long grow = row0 + tid;
        const float invc = 1.0f / g_cnt[grow];
        const int cch = tid >> 2, cw = tid & 3;
        const float4* pb = (const float4*)(g_bta + grow * FF);
        const float4* pa = (const float4*)(atoms + grow * FF);
        #pragma unroll
        for (int q = 0; q < 8; q++) {
            float4 v = __ldg(&pb[q]);
            float vv[4] = {v.x * invc, v.y * invc, v.z * invc, v.w * invc};
            #pragma unroll
            for (int r = 0; r < 4; r++) {
                int k = 4 * q + r;
                sX[k * 128 + (((cch ^ ((k >> 3) & 7)) << 2) | cw)] = vv[r];
            }
        }
        #pragma unroll
        for (int q = 0; q < 8; q++) {
            float4 v = __ldg(&pa[q]);
            float vv[4] = {v.x, v.y, v.z, v.w};
            #pragma unroll
            for (int r = 0; r < 4; r++) {
                int k = 32 + 4 * q + r;
                sX[k * 128 + (((cch ^ ((k >> 3) & 7)) << 2) | cw)] = vv[r];
            }
        }
    }
    __syncthreads();

    u64 acc[8][4];
    #pragma unroll
    for (int s = 0; s < 8; s++)
        #pragma unroll
        for (int jp = 0; jp < 4; jp++) acc[s][jp] = 0ull;

    // ---- layer 1: K=64, vw1 rows 0..63 via __ldg ----
    for (int kk = 0; kk < 64; kk += 8) {
        const int K = kk >> 3;
        const float* xr = &sX[kk * 128];
        #pragma unroll
        for (int u = 0; u < 8; u++) {
            const float4 x0 = *(const float4*)&xr[u * 128 + ((ch0 ^ K) << 2)];
            const float4 x1 = *(const float4*)&xr[u * 128 + (((ch0 + 1) ^ K) << 2)];
            const ulonglong2 wA = __ldg((const ulonglong2*)(w1 + (kk + u) * 64 + j0));
            const ulonglong2 wB = __ldg((const ulonglong2*)(w1 + (kk + u) * 64 + j0 + 4));
            const float xs[8] = {x0.x, x0.y, x0.z, x0.w, x1.x, x1.y, x1.z, x1.w};
            #pragma unroll
            for (int s = 0; s < 8; s++) {
                const u64 x2 = pack2s(xs[s]);
                fma2(acc[s][0], x2, wA.x);
                fma2(acc[s][1], x2, wA.y);
                fma2(acc[s][2], x2, wB.x);
                fma2(acc[s][3], x2, wB.y);
            }
        }
    }
    __syncthreads();

    // ---- epilogue 1: + hst, softplus, transposed store ----
    {
        const float4 hA = *(const float4*)&s_hst[j0];
        const float4 hB = *(const float4*)&s_hst[j0 + 4];
        #pragma unroll
        for (int s = 0; s < 8; s++) {
            float v0, v1;
            unpack2(acc[s][0], v0, v1);
            acc[s][0] = pack2(softplus(v0 + hA.x), softplus(v1 + hA.y));
            unpack2(acc[s][1], v0, v1);
            acc[s][1] = pack2(softplus(v0 + hA.z), softplus(v1 + hA.w));
            unpack2(acc[s][2], v0, v1);
            acc[s][2] = pack2(softplus(v0 + hB.x), softplus(v1 + hB.y));
            unpack2(acc[s][3], v0, v1);
            acc[s][3] = pack2(softplus(v0 + hB.z), softplus(v1 + hB.w));
        }
        #pragma unroll
        for (int jj = 0; jj < 8; jj++) {
            const int r = j0 + jj;
            const int S = (r >> 3) & 7;
            const int jp = jj >> 1;
            float t0, t1, t2, t3, t4, t5, t6, t7, lo, hi;
            unpack2(acc[0][jp], lo, hi); t0 = (jj & 1) ? hi : lo;
            unpack2(acc[1][jp], lo, hi); t1 = (jj & 1) ? hi : lo;
            unpack2(acc[2][jp], lo, hi); t2 = (jj & 1) ? hi : lo;
            unpack2(acc[3][jp], lo, hi); t3 = (jj & 1) ? hi : lo;
            unpack2(acc[4][jp], lo, hi); t4 = (jj & 1) ? hi : lo;
            unpack2(acc[5][jp], lo, hi); t5 = (jj & 1) ? hi : lo;
            unpack2(acc[6][jp], lo, hi); t6 = (jj & 1) ? hi : lo;
            unpack2(acc[7][jp], lo, hi); t7 = (jj & 1) ? hi : lo;
            *(float4*)&sX[r * 128 + ((ch0 ^ S) << 2)] = make_float4(t0, t1, t2, t3);
            *(float4*)&sX[r * 128 + (((ch0 + 1) ^ S) << 2)] = make_float4(t4, t5, t6, t7);
        }
    }
    __syncthreads();

    // ---- layer 2: K=64, W2 smem ----
    #pragma unroll
    for (int s = 0; s < 8; s++)
        #pragma unroll
        for (int jp = 0; jp < 4; jp++) acc[s][jp] = 0ull;
    for (int kk = 0; kk < 64; kk += 8) {
        const int K = kk >> 3;
        const float* xr = &sX[kk * 128];
        const float* wr = &sW2[kk * 64];
        #pragma unroll
        for (int u = 0; u < 8; u++) {
            const float4 x0 = *(const float4*)&xr[u * 128 + ((ch0 ^ K) << 2)];
            const float4 x1 = *(const float4*)&xr[u * 128 + (((ch0 + 1) ^ K) << 2)];
            const ulonglong2 wA = *(const ulonglong2*)&wr[u * 64 + j0];
            const ulonglong2 wB = *(const ulonglong2*)&wr[u * 64 + j0 + 4];
            const float xs[8] = {x0.x, x0.y, x0.z, x0.w, x1.x, x1.y, x1.z, x1.w};
            #pragma unroll
            for (int s = 0; s < 8; s++) {
                const u64 x2 = pack2s(xs[s]);
                fma2(acc[s][0], x2, wA.x);
                fma2(acc[s][1], x2, wA.y);
                fma2(acc[s][2], x2, wB.x);
                fma2(acc[s][3], x2, wB.y);
            }
        }
    }
    __syncthreads();

    // ---- epilogue 2: + b2, softplus, transposed store ----
    {
        float4 bA = __ldg((const float4*)(b2v + j0));
        float4 bB = __ldg((const float4*)(b2v + j0 + 4));
        #pragma unroll
        for (int s = 0; s < 8; s++) {
            float v0, v1;
            unpack2(acc[s][0], v0, v1);
            acc[s][0] = pack2(softplus(v0 + bA.x), softplus(v1 + bA.y));
            unpack2(acc[s][1], v0, v1);
            acc[s][1] = pack2(softplus(v0 + bA.z), softplus(v1 + bA.w));
            unpack2(acc[s][2], v0, v1);
            acc[s][2] = pack2(softplus(v0 + bB.x), softplus(v1 + bB.y));
            unpack2(acc[s][3], v0, v1);
            acc[s][3] = pack2(softplus(v0 + bB.z), softplus(v1 + bB.w));
        }
        #pragma unroll
        for (int jj = 0; jj < 8; jj++) {
            const int r = j0 + jj;
            const int S = (r >> 3) & 7;
            const int jp = jj >> 1;
            float t0, t1, t2, t3, t4, t5, t6, t7, lo, hi;
            unpack2(acc[0][jp], lo, hi); t0 = (jj & 1) ? hi : lo;
            unpack2(acc[1][jp], lo, hi); t1 = (jj & 1) ? hi : lo;
            unpack2(acc[2][jp], lo, hi); t2 = (jj & 1) ? hi : lo;
            unpack2(acc[3][jp], lo, hi); t3 = (jj & 1) ? hi : lo;
            unpack2(acc[4][jp], lo, hi); t4 = (jj & 1) ? hi : lo;
            unpack2(acc[5][jp], lo, hi); t5 = (jj & 1) ? hi : lo;
            unpack2(acc[6][jp], lo, hi); t6 = (jj & 1) ? hi : lo;
            unpack2(acc[7][jp], lo, hi); t7 = (jj & 1) ? hi : lo;
            *(float4*)&sX[r * 128 + ((ch0 ^ S) << 2)] = make_float4(t0, t1, t2, t3);
            *(float4*)&sX[r * 128 + (((ch0 + 1) ^ S) << 2)] = make_float4(t4, t5, t6, t7);
        }
    }
    __syncthreads();

    // ---- layer 3: K=64, N=32 ----
    const int j0b = tj * 4;
    u64 a3[8][2];
    #pragma unroll
    for (int s = 0; s < 8; s++) { a3[s][0] = 0ull; a3[s][1] = 0ull; }
    for (int kk = 0; kk < 64; kk += 8) {
        const int K = kk >> 3;
        const float* xr = &sX[kk * 128];
        #pragma unroll
        for (int u = 0; u < 8; u++) {
            const float4 x0 = *(const float4*)&xr[u * 128 + ((ch0 ^ K) << 2)];
            const float4 x1 = *(const float4*)&xr[u * 128 + (((ch0 + 1) ^ K) << 2)];
            const ulonglong2 wv = __ldg((const ulonglong2*)(w3 + (kk + u) * 32 + j0b));
            const float xs[8] = {x0.x, x0.y, x0.z, x0.w, x1.x, x1.y, x1.z, x1.w};
            #pragma unroll
            for (int s = 0; s < 8; s++) {
                const u64 x2 = pack2s(xs[s]);
                fma2(a3[s][0], x2, wv.x);
                fma2(a3[s][1], x2, wv.y);
            }
        }
    }

    {
        float4 b3q = __ldg((const float4*)(b3v + j0b));
        #pragma unroll
        for (int s = 0; s < 8; s++) {
            const long row = row0 + c0 + s;
            float o0, o1, o2, o3;
            unpack2(a3[s][0], o0, o1);
            unpack2(a3[s][1], o2, o3);
            o0 = softplus(o0 + b3q.x);
            o1 = softplus(o1 + b3q.y);
            o2 = softplus(o2 + b3q.z);
            o3 = softplus(o3 + b3q.w);
            *(float4*)(out_atoms + row * FF + j0b) = make_float4(o0, o1, o2, o3);
        }
    }
}

// ---------------- reduce kernel: batch sums of g_bta (=bond sums) and out_atoms ----------------
__global__ void __launch_bounds__(256) reduce_kernel(const float* __restrict__ out_atoms) {
    __shared__ float red[2][8][32];
    const int blk = blockIdx.x;       // BB * 8 blocks
    const int b = blk >> 3;
    const int seg = blk & 7;
    const int t = threadIdx.x;
    const int f = t & 31;
    const int g = t >> 5;
    const long base = ((long)b * NATM + seg * 1024) * FF;
    float sb = 0.0f, sa = 0.0f;
    for (int r = g; r < 1024; r += 8) {
        sb += g_bta[base + (long)r * FF + f];
        sa += __ldg(&out_atoms[base + (long)r * FF + f]);
    }
    red[0][g][f] = sb;
    red[1][g][f] = sa;
    __syncthreads();
    if (g == 0) {
        float vb = 0.0f, va = 0.0f;
        #pragma unroll
        for (int i = 0; i < 8; i++) { vb += red[0][i][f]; va += red[1][i][f]; }
        atomicAdd(&g_bond_sum[b * FF + f], vb);
        atomicAdd(&g_atom_sum[b * FF + f], va);
    }
}

// ---------------- state kernel ----------------
__global__ void __launch_bounds__(64) state_kernel(
    const float* __restrict__ state,
    const float* __restrict__ w1, const float* __restrict__ b1,
    const float* __restrict__ w2, const float* __restrict__ b2,
    const float* __restrict__ w3, const float* __restrict__ b3,
    float* __restrict__ out_state)
{
    __shared__ float u_in[96];
    __shared__ float h1s[64];
    __shared__ float h2s[64];
    const int b = blockIdx.x;
    const int t = threadIdx.x;
    if (t < 32) {
        u_in[t]      = g_bond_sum[b * FF + t] * (1.0f / NBND);
        u_in[32 + t] = g_atom_sum[b * FF + t] * (1.0f / NATM);
        u_in[64 + t] = state[b * FF + t];
    }
    __syncthreads();
    {
        float acc = __ldg(&b1[t]);
        for (int k = 0; k < 96; k++) acc = fmaf(u_in[k], __ldg(&w1[k * 64 + t]), acc);
        h1s[t] = softplus(acc);
    }
    __syncthreads();
    {
        float acc = __ldg(&b2[t]);
        for (int k = 0; k < 64; k++) acc = fmaf(h1s[k], __ldg(&w2[k * 64 + t]), acc);
        h2s[t] = softplus(acc);
    }
    __syncthreads();
    if (t < 32) {
        float acc = __ldg(&b3[t]);
        for (int k = 0; k < 64; k++) acc = fmaf(h2s[k], __ldg(&w3[k * 32 + t]), acc);
        out_state[b * FF + t] = softplus(acc);
    }
}

extern "C" void kernel_launch(void* const* d_in, const int* in_sizes, int n_in,
                              void* d_out, int out_size)
{
    const float* bonds = (const float*)d_in[0];
    const int*   ba1   = (const int*)d_in[1];
    const int*   ba2   = (const int*)d_in[2];
    const float* atoms = (const float*)d_in[3];
    const float* state = (const float*)d_in[4];
    const float* ew1 = (const float*)d_in[5];
    const float* eb1 = (const float*)d_in[6];
    const float* ew2 = (const float*)d_in[7];
    const float* eb2 = (const float*)d_in[8];
    const float* ew3 = (const float*)d_in[9];
    const float* eb3 = (const float*)d_in[10];
    const float* vw1 = (const float*)d_in[11];
    const float* vb1 = (const float*)d_in[12];
    const float* vw2 = (const float*)d_in[13];
    const float* vb2 = (const float*)d_in[14];
    const float* vw3 = (const float*)d_in[15];
    const float* vb3 = (const float*)d_in[16];
    const float* uw1 = (const float*)d_in[17];
    const float* ub1 = (const float*)d_in[18];
    const float* uw2 = (const float*)d_in[19];
    const float* ub2 = (const float*)d_in[20];
    const float* uw3 = (const float*)d_in[21];
    const float* ub3 = (const float*)d_in[22];

    float* out = (float*)d_out;
    float* out_bonds = out;
    float* out_atoms = out + (long)BB * NBND * FF;
    float* out_state = out_atoms + (long)BB * NATM * FF;

    zero_kernel<<<(BB * NATM * FF + 255) / 256, 256>>>();
    atom_pre_kernel<<<(BB * NATM) / 128, 128>>>(atoms, ew1, eb1, state);
    bond_kernel<<<(BB * NBND) / 128, 128>>>(bonds, ba1, ba2,
                                            ew1, ew2, eb2, ew3, eb3, out_bonds);
    atom_main_kernel<<<(BB * NATM) / 128, 128>>>(atoms, state,
                                                 vw1, vb1, vw2, vb2, vw3, vb3, out_atoms);
    reduce_kernel<<<BB * 8, 256>>>(out_atoms);
    state_kernel<<<BB, 64>>>(state, uw1, ub1, uw2, ub2, uw3, ub3, out_state);
}

// round 13
// speedup vs baseline: 1.4293x; 1.0127x over previous
#include <cuda_runtime.h>
#include <cuda_bf16.h>

#define BB 4
#define NBND 262144
#define NATM 8192
#define FF 32

typedef unsigned long long u64;

__device__ float g_bta[BB * NATM * FF];
__device__ float g_cnt[BB * NATM];
__device__ float g_bond_sum[BB * FF];
__device__ float g_atom_sum[BB * FF];
__device__ __align__(16) float g_pa[BB * NATM * 64];  // hst + atoms@W1[0:32]
__device__ __align__(16) float g_pb[BB * NATM * 64];  // atoms@W1[32:64]

__device__ __forceinline__ float softplus(float x) {
    return fmaxf(x, 0.0f) + __logf(1.0f + __expf(-fabsf(x)));
}
__device__ __forceinline__ u64 pack2(float lo, float hi) {
    u64 r; asm("mov.b64 %0, {%1, %2};" : "=l"(r) : "f"(lo), "f"(hi)); return r;
}
__device__ __forceinline__ u64 pack2s(float x) { return pack2(x, x); }
__device__ __forceinline__ void unpack2(u64 v, float& lo, float& hi) {
    asm("mov.b64 {%0, %1}, %2;" : "=f"(lo), "=f"(hi) : "l"(v));
}
__device__ __forceinline__ void fma2(u64& d, u64 a, u64 b) {
    asm("fma.rn.f32x2 %0, %1, %2, %0;" : "+l"(d) : "l"(a), "l"(b));
}
__device__ __forceinline__ void red4(float* p, float a, float b, float c, float d) {
    asm volatile("red.global.add.v4.f32 [%0], {%1, %2, %3, %4};"
                 :: "l"(p), "f"(a), "f"(b), "f"(c), "f"(d) : "memory");
}

__global__ void zero_kernel() {
    long i = (long)blockIdx.x * 256 + threadIdx.x;
    if (i < (long)BB * NATM * FF) g_bta[i] = 0.0f;
    if (i < BB * NATM) g_cnt[i] = 0.0f;
    if (i < BB * FF) { g_bond_sum[i] = 0.0f; g_atom_sum[i] = 0.0f; }
}

// ---------------- atom_pre: warp-tiled, block = 128 atoms ----------------
// warp = 32 atoms x 64 outs; thread = 8 atoms x 8 outs; two passes (pa, pb).
__global__ void __launch_bounds__(128, 4) atom_pre_kernel(
    const float* __restrict__ atoms, const float* __restrict__ w1,
    const float* __restrict__ b1, const float* __restrict__ state)
{
    __shared__ __align__(16) float sX[32 * 128];   // 16 KB (atom features, swizzled)
    __shared__ __align__(16) float s_hst[64];

    const int tid = threadIdx.x;
    const int w = tid >> 5;
    const int lane = tid & 31;
    const int ti = lane & 3;
    const int tj = lane >> 2;
    const int j0 = tj * 8;
    const int c0 = w * 32 + ti * 8;
    const int ch0 = c0 >> 2;
    const long row0 = (long)blockIdx.x * 128;
    const int b = blockIdx.x >> 6;     // 64 blocks per batch

    if (tid < 64) {
        float acc = __ldg(&b1[tid]);
        #pragma unroll
        for (int k = 0; k < 32; k++)
            acc = fmaf(__ldg(&state[b * FF + k]), __ldg(&w1[(96 + k) * 64 + tid]), acc);
        s_hst[tid] = acc;
    }

    // stage atom features into sX rows 0..31 (swizzled)
    {
        const float4* p = (const float4*)(atoms + (row0 + tid) * FF);
        const int cch = tid >> 2, cw = tid & 3;
        #pragma unroll
        for (int q = 0; q < 8; q++) {
            float4 v = __ldg(&p[q]);
            float vv[4] = {v.x, v.y, v.z, v.w};
            #pragma unroll
            for (int r = 0; r < 4; r++) {
                int k = 4 * q + r;
                sX[k * 128 + (((cch ^ ((k >> 3) & 7)) << 2) | cw)] = vv[r];
            }
        }
    }
    __syncthreads();

    u64 acc[8][4];

    // ---- pass A: pa = hst + x @ W1[0:32] ----
    {
        const float4 hA = *(const float4*)&s_hst[j0];
        const float4 hB = *(const float4*)&s_hst[j0 + 4];
        #pragma unroll
        for (int s = 0; s < 8; s++) {
            acc[s][0] = pack2(hA.x, hA.y);
            acc[s][1] = pack2(hA.z, hA.w);
            acc[s][2] = pack2(hB.x, hB.y);
            acc[s][3] = pack2(hB.z, hB.w);
        }
    }
    #pragma unroll 4
    for (int k = 0; k < 32; k++) {
        const int K = (k >> 3) & 7;
        const float4 x0 = *(const float4*)&sX[k * 128 + ((ch0 ^ K) << 2)];
        const float4 x1 = *(const float4*)&sX[k * 128 + (((ch0 + 1) ^ K) << 2)];
        const ulonglong2 wA = __ldg((const ulonglong2*)(w1 + k * 64 + j0));
        const ulonglong2 wB = __ldg((const ulonglong2*)(w1 + k * 64 + j0 + 4));
        const float xs[8] = {x0.x, x0.y, x0.z, x0.w, x1.x, x1.y, x1.z, x1.w};
        #pragma unroll
        for (int s = 0; s < 8; s++) {
            const u64 x2 = pack2s(xs[s]);
            fma2(acc[s][0], x2, wA.x);
            fma2(acc[s][1], x2, wA.y);
            fma2(acc[s][2], x2, wB.x);
            fma2(acc[s][3], x2, wB.y);
        }
    }
    #pragma unroll
    for (int s = 0; s < 8; s++) {
        float* dst = g_pa + (row0 + c0 + s) * 64 + j0;
        float v0, v1, v2, v3;
        unpack2(acc[s][0], v0, v1);
        unpack2(acc[s][1], v2, v3);
        *(float4*)dst = make_float4(v0, v1, v2, v3);
        unpack2(acc[s][2], v0, v1);
        unpack2(acc[s][3], v2, v3);
        *(float4*)(dst + 4) = make_float4(v0, v1, v2, v3);
    }

    // ---- pass B: pb = x @ W1[32:64] ----
    #pragma unroll
    for (int s = 0; s < 8; s++)
        #pragma unroll
        for (int jp = 0; jp < 4; jp++) acc[s][jp] = 0ull;
    #pragma unroll 4
    for (int k = 0; k < 32; k++) {
        const int K = (k >> 3) & 7;
        const float4 x0 = *(const float4*)&sX[k * 128 + ((ch0 ^ K) << 2)];
        const float4 x1 = *(const float4*)&sX[k * 128 + (((ch0 + 1) ^ K) << 2)];
        const ulonglong2 wA = __ldg((const ulonglong2*)(w1 + (32 + k) * 64 + j0));
        const ulonglong2 wB = __ldg((const ulonglong2*)(w1 + (32 + k) * 64 + j0 + 4));
        const float xs[8] = {x0.x, x0.y, x0.z, x0.w, x1.x, x1.y, x1.z, x1.w};
        #pragma unroll
        for (int s = 0; s < 8; s++) {
            const u64 x2 = pack2s(xs[s]);
            fma2(acc[s][0], x2, wA.x);
            fma2(acc[s][1], x2, wA.y);
            fma2(acc[s][2], x2, wB.x);
            fma2(acc[s][3], x2, wB.y);
        }
    }
    #pragma unroll
    for (int s = 0; s < 8; s++) {
        float* dst = g_pb + (row0 + c0 + s) * 64 + j0;
        float v0, v1, v2, v3;
        unpack2(acc[s][0], v0, v1);
        unpack2(acc[s][1], v2, v3);
        *(float4*)dst = make_float4(v0, v1, v2, v3);
        unpack2(acc[s][2], v0, v1);
        unpack2(acc[s][3], v2, v3);
        *(float4*)(dst + 4) = make_float4(v0, v1, v2, v3);
    }
}

// ---------------- bond kernel: round-10 proven version (429 us) ----------------
__global__ void __launch_bounds__(128, 4) bond_kernel(
    const float* __restrict__ bonds, const int* __restrict__ ba1,
    const int* __restrict__ ba2,
    const float* __restrict__ w1, const float* __restrict__ w2,
    const float* __restrict__ b2v, const float* __restrict__ w3,
    const float* __restrict__ b3v, float* __restrict__ out_bonds)
{
    __shared__ __align__(16) float sW2[64 * 64];
    __shared__ __align__(16) float sX[64 * 128];

    const int tid = threadIdx.x;
    const int w = tid >> 5;
    const int lane = tid & 31;
    const int ti = lane & 3;
    const int tj = lane >> 2;
    const int j0 = tj * 8;
    const int c0 = w * 32 + ti * 8;
    const int ch0 = c0 >> 2;
    const long row0 = (long)blockIdx.x * 128;
    const int b = blockIdx.x >> 11;

    for (int i = tid; i < 1024; i += 128)
        ((float4*)sW2)[i] = __ldg(&((const float4*)w2)[i]);

    {
        const float4* p = (const float4*)(bonds + (row0 + tid) * FF);
        const int cch = tid >> 2, cw = tid & 3;
        #pragma unroll
        for (int q = 0; q < 8; q++) {
            float4 v = __ldg(&p[q]);
            float vv[4] = {v.x, v.y, v.z, v.w};
            #pragma unroll
            for (int r = 0; r < 4; r++) {
                int k = 4 * q + r;
                sX[k * 128 + (((cch ^ ((k >> 3) & 7)) << 2) | cw)] = vv[r];
            }
        }
    }
    __syncthreads();

    u64 acc[8][4];
    #pragma unroll
    for (int s = 0; s < 8; s++)
        #pragma unroll
        for (int jp = 0; jp < 4; jp++) acc[s][jp] = 0ull;

    #pragma unroll 4
    for (int k = 0; k < 32; k++) {
        const int K = (k >> 3) & 7;
        const float4 x0 = *(const float4*)&sX[k * 128 + ((ch0 ^ K) << 2)];
        const float4 x1 = *(const float4*)&sX[k * 128 + (((ch0 + 1) ^ K) << 2)];
        const ulonglong2 wA = __ldg((const ulonglong2*)(w1 + (64 + k) * 64 + j0));
        const ulonglong2 wB = __ldg((const ulonglong2*)(w1 + (64 + k) * 64 + j0 + 4));
        const float xs[8] = {x0.x, x0.y, x0.z, x0.w, x1.x, x1.y, x1.z, x1.w};
        #pragma unroll
        for (int s = 0; s < 8; s++) {
            const u64 x2 = pack2s(xs[s]);
            fma2(acc[s][0], x2, wA.x);
            fma2(acc[s][1], x2, wA.y);
            fma2(acc[s][2], x2, wB.x);
            fma2(acc[s][3], x2, wB.y);
        }
    }
    __syncthreads();

    #pragma unroll
    for (int s = 0; s < 8; s++) {
        const long row = row0 + c0 + s;
        const int a1 = __ldg(&ba1[row]);
        const int a2 = __ldg(&ba2[row]);
        const float* pap = g_pa + ((long)b * NATM + a1) * 64 + j0;
        const float* pbp = g_pb + ((long)b * NATM + a2) * 64 + j0;
        float4 A0 = __ldg((const float4*)pap), A1 = __ldg((const float4*)(pap + 4));
        float4 B0 = __ldg((const float4*)pbp), B1 = __ldg((const float4*)(pbp + 4));
        float v0, v1;
        unpack2(acc[s][0], v0, v1);
        acc[s][0] = pack2(softplus(v0 + A0.x + B0.x), softplus(v1 + A0.y + B0.y));
        unpack2(acc[s][1], v0, v1);
        acc[s][1] = pack2(softplus(v0 + A0.z + B0.z), softplus(v1 + A0.w + B0.w));
        unpack2(acc[s][2], v0, v1);
        acc[s][2] = pack2(softplus(v0 + A1.x + B1.x), softplus(v1 + A1.y + B1.y));
        unpack2(acc[s][3], v0, v1);
        acc[s][3] = pack2(softplus(v0 + A1.z + B1.z), softplus(v1 + A1.w + B1.w));
    }
    #pragma unroll
    for (int jj = 0; jj < 8; jj++) {
        const int r = j0 + jj;
        const int S = (r >> 3) & 7;
        const int jp = jj >> 1;
        float t0, t1, t2, t3, t4, t5, t6, t7, lo, hi;
        unpack2(acc[0][jp], lo, hi); t0 = (jj & 1) ? hi : lo;
        unpack2(acc[1][jp], lo, hi); t1 = (jj & 1) ? hi : lo;
        unpack2(acc[2][jp], lo, hi); t2 = (jj & 1) ? hi : lo;
        unpack2(acc[3][jp], lo, hi); t3 = (jj & 1) ? hi : lo;
        unpack2(acc[4][jp], lo, hi); t4 = (jj & 1) ? hi : lo;
        unpack2(acc[5][jp], lo, hi); t5 = (jj & 1) ? hi : lo;
        unpack2(acc[6][jp], lo, hi); t6 = (jj & 1) ? hi : lo;
        unpack2(acc[7][jp], lo, hi); t7 = (jj & 1) ? hi : lo;
        *(float4*)&sX[r * 128 + ((ch0 ^ S) << 2)] = make_float4(t0, t1, t2, t3);
        *(float4*)&sX[r * 128 + (((ch0 + 1) ^ S) << 2)] = make_float4(t4, t5, t6, t7);
    }
    __syncthreads();

    #pragma unroll
    for (int s = 0; s < 8; s++)
        #pragma unroll
        for (int jp = 0; jp < 4; jp++) acc[s][jp] = 0ull;
    for (int kk = 0; kk < 64; kk += 8) {
        const int K = kk >> 3;
        const float* xr = &sX[kk * 128];
        const float* wr = &sW2[kk * 64];
        #pragma unroll
        for (int u = 0; u < 8; u++) {
            const float4 x0 = *(const float4*)&xr[u * 128 + ((ch0 ^ K) << 2)];
            const float4 x1 = *(const float4*)&xr[u * 128 + (((ch0 + 1) ^ K) << 2)];
            const ulonglong2 wA = *(const ulonglong2*)&wr[u * 64 + j0];
            const ulonglong2 wB = *(const ulonglong2*)&wr[u * 64 + j0 + 4];
            const float xs[8] = {x0.x, x0.y, x0.z, x0.w, x1.x, x1.y, x1.z, x1.w};
            #pragma unroll
            for (int s = 0; s < 8; s++) {
                const u64 x2 = pack2s(xs[s]);
                fma2(acc[s][0], x2, wA.x);
                fma2(acc[s][1], x2, wA.y);
                fma2(acc[s][2], x2, wB.x);
                fma2(acc[s][3], x2, wB.y);
            }
        }
    }
    __syncthreads();

    {
        float4 bA = __ldg((const float4*)(b2v + j0));
        float4 bB = __ldg((const float4*)(b2v + j0 + 4));
        #pragma unroll
        for (int s = 0; s < 8; s++) {
            float v0, v1;
            unpack2(acc[s][0], v0, v1);
            acc[s][0] = pack2(softplus(v0 + bA.x), softplus(v1 + bA.y));
            unpack2(acc[s][1], v0, v1);
            acc[s][1] = pack2(softplus(v0 + bA.z), softplus(v1 + bA.w));
            unpack2(acc[s][2], v0, v1);
            acc[s][2] = pack2(softplus(v0 + bB.x), softplus(v1 + bB.y));
            unpack2(acc[s][3], v0, v1);
            acc[s][3] = pack2(softplus(v0 + bB.z), softplus(v1 + bB.w));
        }
        #pragma unroll
        for (int jj = 0; jj < 8; jj++) {
            const int r = j0 + jj;
            const int S = (r >> 3) & 7;
            const int jp = jj >> 1;
            float t0, t1, t2, t3, t4, t5, t6, t7, lo, hi;
            unpack2(acc[0][jp], lo, hi); t0 = (jj & 1) ? hi : lo;
            unpack2(acc[1][jp], lo, hi); t1 = (jj & 1) ? hi : lo;
            unpack2(acc[2][jp], lo, hi); t2 = (jj & 1) ? hi : lo;
            unpack2(acc[3][jp], lo, hi); t3 = (jj & 1) ? hi : lo;
            unpack2(acc[4][jp], lo, hi); t4 = (jj & 1) ? hi : lo;
            unpack2(acc[5][jp], lo, hi); t5 = (jj & 1) ? hi : lo;
            unpack2(acc[6][jp], lo, hi); t6 = (jj & 1) ? hi : lo;
            unpack2(acc[7][jp], lo, hi); t7 = (jj & 1) ? hi : lo;
            *(float4*)&sX[r * 128 + ((ch0 ^ S) << 2)] = make_float4(t0, t1, t2, t3);
            *(float4*)&sX[r * 128 + (((ch0 + 1) ^ S) << 2)] = make_float4(t4, t5, t6, t7);
        }
    }
    __syncthreads();

    const int j0b = tj * 4;
    u64 a3[8][2];
    #pragma unroll
    for (int s = 0; s < 8; s++) { a3[s][0] = 0ull; a3[s][1] = 0ull; }
    for (int kk = 0; kk < 64; kk += 8) {
        const int K = kk >> 3;
        const float* xr = &sX[kk * 128];
        #pragma unroll
        for (int u = 0; u < 8; u++) {
            const float4 x0 = *(const float4*)&xr[u * 128 + ((ch0 ^ K) << 2)];
            const float4 x1 = *(const float4*)&xr[u * 128 + (((ch0 + 1) ^ K) << 2)];
            const ulonglong2 wv = __ldg((const ulonglong2*)(w3 + (kk + u) * 32 + j0b));
            const float xs[8] = {x0.x, x0.y, x0.z, x0.w, x1.x, x1.y, x1.z, x1.w};
            #pragma unroll
            for (int s = 0; s < 8; s++) {
                const u64 x2 = pack2s(xs[s]);
                fma2(a3[s][0], x2, wv.x);
                fma2(a3[s][1], x2, wv.y);
            }
        }
    }

    {
        float4 b3q = __ldg((const float4*)(b3v + j0b));
        #pragma unroll
        for (int s = 0; s < 8; s++) {
            const long row = row0 + c0 + s;
            const int a1 = __ldg(&ba1[row]);
            float o0, o1, o2, o3;
            unpack2(a3[s][0], o0, o1);
            unpack2(a3[s][1], o2, o3);
            o0 = softplus(o0 + b3q.x);
            o1 = softplus(o1 + b3q.y);
            o2 = softplus(o2 + b3q.z);
            o3 = softplus(o3 + b3q.w);
            *(float4*)(out_bonds + row * FF + j0b) = make_float4(o0, o1, o2, o3);
            red4(g_bta + ((long)b * NATM + a1) * FF + j0b, o0, o1, o2, o3);
            if (tj == 0) atomicAdd(&g_cnt[b * NATM + a1], 1.0f);
        }
    }
}

// ---------------- atom main kernel (round-12 proven) ----------------
__global__ void __launch_bounds__(128, 4) atom_main_kernel(
    const float* __restrict__ atoms, const float* __restrict__ state,
    const float* __restrict__ w1, const float* __restrict__ b1,
    const float* __restrict__ w2, const float* __restrict__ b2v,
    const float* __restrict__ w3, const float* __restrict__ b3v,
    float* __restrict__ out_atoms)
{
    __shared__ __align__(16) float sW2[64 * 64];
    __shared__ __align__(16) float sX[64 * 128];
    __shared__ __align__(16) float s_hst[64];

    const int tid = threadIdx.x;
    const int w = tid >> 5;
    const int lane = tid & 31;
    const int ti = lane & 3;
    const int tj = lane >> 2;
    const int j0 = tj * 8;
    const int c0 = w * 32 + ti * 8;
    const int ch0 = c0 >> 2;
    const long row0 = (long)blockIdx.x * 128;
    const int b = blockIdx.x >> 6;

    for (int i = tid; i < 1024; i += 128)
        ((float4*)sW2)[i] = __ldg(&((const float4*)w2)[i]);

    if (tid < 64) {
        float acc = __ldg(&b1[tid]);
        #pragma unroll
        for (int k = 0; k < 32; k++)
            acc = fmaf(__ldg(&state[b * FF + k]), __ldg(&w1[(64 + k) * 64 + tid]), acc);
        s_hst[tid] = acc;
    }

    {
        const long grow = row0 + tid;
        const float invc = 1.0f / g_cnt[grow];
        const int cch = tid >> 2, cw = tid & 3;
        const float4* pb = (const float4*)(g_bta + grow * FF);
        const float4* pa = (const float4*)(atoms + grow * FF);
        #pragma unroll
        for (int q = 0; q < 8; q++) {
            float4 v = __ldg(&pb[q]);
            float vv[4] = {v.x * invc, v.y * invc, v.z * invc, v.w * invc};
            #pragma unroll
            for (int r = 0; r < 4; r++) {
                int k = 4 * q + r;
                sX[k * 128 + (((cch ^ ((k >> 3) & 7)) << 2) | cw)] = vv[r];
            }
        }
        #pragma unroll
        for (int q = 0; q < 8; q++) {
            float4 v = __ldg(&pa[q]);
            float vv[4] = {v.x, v.y, v.z, v.w};
            #pragma unroll
            for (int r = 0; r < 4; r++) {
                int k = 32 + 4 * q + r;
                sX[k * 128 + (((cch ^ ((k >> 3) & 7)) << 2) | cw)] = vv[r];
            }
        }
    }
    __syncthreads();

    u64 acc[8][4];
    #pragma unroll
    for (int s = 0; s < 8; s++)
        #pragma unroll
        for (int jp = 0; jp < 4; jp++) acc[s][jp] = 0ull;

    for (int kk = 0; kk < 64; kk += 8) {
        const int K = kk >> 3;
        const float* xr = &sX[kk * 128];
        #pragma unroll
        for (int u = 0; u < 8; u++) {
            const float4 x0 = *(const float4*)&xr[u * 128 + ((ch0 ^ K) << 2)];
            const float4 x1 = *(const float4*)&xr[u * 128 + (((ch0 + 1) ^ K) << 2)];
            const ulonglong2 wA = __ldg((const ulonglong2*)(w1 + (kk + u) * 64 + j0));
            const ulonglong2 wB = __ldg((const ulonglong2*)(w1 + (kk + u) * 64 + j0 + 4));
            const float xs[8] = {x0.x, x0.y, x0.z, x0.w, x1.x, x1.y, x1.z, x1.w};
            #pragma unroll
            for (int s = 0; s < 8; s++) {
                const u64 x2 = pack2s(xs[s]);
                fma2(acc[s][0], x2, wA.x);
                fma2(acc[s][1], x2, wA.y);
                fma2(acc[s][2], x2, wB.x);
                fma2(acc[s][3], x2, wB.y);
            }
        }
    }
    __syncthreads();

    {
        const float4 hA = *(const float4*)&s_hst[j0];
        const float4 hB = *(const float4*)&s_hst[j0 + 4];
        #pragma unroll
        for (int s = 0; s < 8; s++) {
            float v0, v1;
            unpack2(acc[s][0], v0, v1);
            acc[s][0] = pack2(softplus(v0 + hA.x), softplus(v1 + hA.y));
            unpack2(acc[s][1], v0, v1);
            acc[s][1] = pack2(softplus(v0 + hA.z), softplus(v1 + hA.w));
            unpack2(acc[s][2], v0, v1);
            acc[s][2] = pack2(softplus(v0 + hB.x), softplus(v1 + hB.y));
            unpack2(acc[s][3], v0, v1);
            acc[s][3] = pack2(softplus(v0 + hB.z), softplus(v1 + hB.w));
        }
        #pragma unroll
        for (int jj = 0; jj < 8; jj++) {
            const int r = j0 + jj;
            const int S = (r >> 3) & 7;
            const int jp = jj >> 1;
            float t0, t1, t2, t3, t4, t5, t6, t7, lo, hi;
            unpack2(acc[0][jp], lo, hi); t0 = (jj & 1) ? hi : lo;
            unpack2(acc[1][jp], lo, hi); t1 = (jj & 1) ? hi : lo;
            unpack2(acc[2][jp], lo, hi); t2 = (jj & 1) ? hi : lo;
            unpack2(acc[3][jp], lo, hi); t3 = (jj & 1) ? hi : lo;
            unpack2(acc[4][jp], lo, hi); t4 = (jj & 1) ? hi : lo;
            unpack2(acc[5][jp], lo, hi); t5 = (jj & 1) ? hi : lo;
            unpack2(acc[6][jp], lo, hi); t6 = (jj & 1) ? hi : lo;
            unpack2(acc[7][jp], lo, hi); t7 = (jj & 1) ? hi : lo;
            *(float4*)&sX[r * 128 + ((ch0 ^ S) << 2)] = make_float4(t0, t1, t2, t3);
            *(float4*)&sX[r * 128 + (((ch0 + 1) ^ S) << 2)] = make_float4(t4, t5, t6, t7);
        }
    }
    __syncthreads();

    #pragma unroll
    for (int s = 0; s < 8; s++)
        #pragma unroll
        for (int jp = 0; jp < 4; jp++) acc[s][jp] = 0ull;
    for (int kk = 0; kk < 64; kk += 8) {
        const int K = kk >> 3;
        const float* xr = &sX[kk * 128];
        const float* wr = &sW2[kk * 64];
        #pragma unroll
        for (int u = 0; u < 8; u++) {
            const float4 x0 = *(const float4*)&xr[u * 128 + ((ch0 ^ K) << 2)];
            const float4 x1 = *(const float4*)&xr[u * 128 + (((ch0 + 1) ^ K) << 2)];
            const ulonglong2 wA = *(const ulonglong2*)&wr[u * 64 + j0];
            const ulonglong2 wB = *(const ulonglong2*)&wr[u * 64 + j0 + 4];
            const float xs[8] = {x0.x, x0.y, x0.z, x0.w, x1.x, x1.y, x1.z, x1.w};
            #pragma unroll
            for (int s = 0; s < 8; s++) {
                const u64 x2 = pack2s(xs[s]);
                fma2(acc[s][0], x2, wA.x);
                fma2(acc[s][1], x2, wA.y);
                fma2(acc[s][2], x2, wB.x);
                fma2(acc[s][3], x2, wB.y);
            }
        }
    }
    __syncthreads();

    {
        float4 bA = __ldg((const float4*)(b2v + j0));
        float4 bB = __ldg((const float4*)(b2v + j0 + 4));
        #pragma unroll
        for (int s = 0; s < 8; s++) {
            float v0, v1;
            unpack2(acc[s][0], v0, v1);
            acc[s][0] = pack2(softplus(v0 + bA.x), softplus(v1 + bA.y));
            unpack2(acc[s][1], v0, v1);
            acc[s][1] = pack2(softplus(v0 + bA.z), softplus(v1 + bA.w));
            unpack2(acc[s][2], v0, v1);
            acc[s][2] = pack2(softplus(v0 + bB.x), softplus(v1 + bB.y));
            unpack2(acc[s][3], v0, v1);
            acc[s][3] = pack2(softplus(v0 + bB.z), softplus(v1 + bB.w));
        }
        #pragma unroll
        for (int jj = 0; jj < 8; jj++) {
            const int r = j0 + jj;
            const int S = (r >> 3) & 7;
            const int jp = jj >> 1;
            float t0, t1, t2, t3, t4, t5, t6, t7, lo, hi;
            unpack2(acc[0][jp], lo, hi); t0 = (jj & 1) ? hi : lo;
            unpack2(acc[1][jp], lo, hi); t1 = (jj & 1) ? hi : lo;
            unpack2(acc[2][jp], lo, hi); t2 = (jj & 1) ? hi : lo;
            unpack2(acc[3][jp], lo, hi); t3 = (jj & 1) ? hi : lo;
            unpack2(acc[4][jp], lo, hi); t4 = (jj & 1) ? hi : lo;
            unpack2(acc[5][jp], lo, hi); t5 = (jj & 1) ? hi : lo;
            unpack2(acc[6][jp], lo, hi); t6 = (jj & 1) ? hi : lo;
            unpack2(acc[7][jp], lo, hi); t7 = (jj & 1) ? hi : lo;
            *(float4*)&sX[r * 128 + ((ch0 ^ S) << 2)] = make_float4(t0, t1, t2, t3);
            *(float4*)&sX[r * 128 + (((ch0 + 1) ^ S) << 2)] = make_float4(t4, t5, t6, t7);
        }
    }
    __syncthreads();

    const int j0b = tj * 4;
    u64 a3[8][2];
    #pragma unroll
    for (int s = 0; s < 8; s++) { a3[s][0] = 0ull; a3[s][1] = 0ull; }
    for (int kk = 0; kk < 64; kk += 8) {
        const int K = kk >> 3;
        const float* xr = &sX[kk * 128];
        #pragma unroll
        for (int u = 0; u < 8; u++) {
            const float4 x0 = *(const float4*)&xr[u * 128 + ((ch0 ^ K) << 2)];
            const float4 x1 = *(const float4*)&xr[u * 128 + (((ch0 + 1) ^ K) << 2)];
            const ulonglong2 wv = __ldg((const ulonglong2*)(w3 + (kk + u) * 32 + j0b));
            const float xs[8] = {x0.x, x0.y, x0.z, x0.w, x1.x, x1.y, x1.z, x1.w};
            #pragma unroll
            for (int s = 0; s < 8; s++) {
                const u64 x2 = pack2s(xs[s]);
                fma2(a3[s][0], x2, wv.x);
                fma2(a3[s][1], x2, wv.y);
            }
        }
    }

    {
        float4 b3q = __ldg((const float4*)(b3v + j0b));
        #pragma unroll
        for (int s = 0; s < 8; s++) {
            const long row = row0 + c0 + s;
            float o0, o1, o2, o3;
            unpack2(a3[s][0], o0, o1);
            unpack2(a3[s][1], o2, o3);
            o0 = softplus(o0 + b3q.x);
            o1 = softplus(o1 + b3q.y);
            o2 = softplus(o2 + b3q.z);
            o3 = softplus(o3 + b3q.w);
            *(float4*)(out_atoms + row * FF + j0b) = make_float4(o0, o1, o2, o3);
        }
    }
}

// ---------------- reduce kernel ----------------
__global__ void __launch_bounds__(256) reduce_kernel(const float* __restrict__ out_atoms) {
    __shared__ float red[2][8][32];
    const int blk = blockIdx.x;
    const int b = blk >> 3;
    const int seg = blk & 7;
    const int t = threadIdx.x;
    const int f = t & 31;
    const int g = t >> 5;
    const long base = ((long)b * NATM + seg * 1024) * FF;
    float sb = 0.0f, sa = 0.0f;
    for (int r = g; r < 1024; r += 8) {
        sb += g_bta[base + (long)r * FF + f];
        sa += __ldg(&out_atoms[base + (long)r * FF + f]);
    }
    red[0][g][f] = sb;
    red[1][g][f] = sa;
    __syncthreads();
    if (g == 0) {
        float vb = 0.0f, va = 0.0f;
        #pragma unroll
        for (int i = 0; i < 8; i++) { vb += red[0][i][f]; va += red[1][i][f]; }
        atomicAdd(&g_bond_sum[b * FF + f], vb);
        atomicAdd(&g_atom_sum[b * FF + f], va);
    }
}

// ---------------- state kernel ----------------
__global__ void __launch_bounds__(64) state_kernel(
    const float* __restrict__ state,
    const float* __restrict__ w1, const float* __restrict__ b1,
    const float* __restrict__ w2, const float* __restrict__ b2,
    const float* __restrict__ w3, const float* __restrict__ b3,
    float* __restrict__ out_state)
{
    __shared__ float u_in[96];
    __shared__ float h1s[64];
    __shared__ float h2s[64];
    const int b = blockIdx.x;
    const int t = threadIdx.x;
    if (t < 32) {
        u_in[t]      = g_bond_sum[b * FF + t] * (1.0f / NBND);
        u_in[32 + t] = g_atom_sum[b * FF + t] * (1.0f / NATM);
        u_in[64 + t] = state[b * FF + t];
    }
    __syncthreads();
    {
        float acc = __ldg(&b1[t]);
        for (int k = 0; k < 96; k++) acc = fmaf(u_in[k], __ldg(&w1[k * 64 + t]), acc);
        h1s[t] = softplus(acc);
    }
    __syncthreads();
    {
        float acc = __ldg(&b2[t]);
        for (int k = 0; k < 64; k++) acc = fmaf(h1s[k], __ldg(&w2[k * 64 + t]), acc);
        h2s[t] = softplus(acc);
    }
    __syncthreads();
    if (t < 32) {
        float acc = __ldg(&b3[t]);
        for (int k = 0; k < 64; k++) acc = fmaf(h2s[k], __ldg(&w3[k * 32 + t]), acc);
        out_state[b * FF + t] = softplus(acc);
    }
}

extern "C" void kernel_launch(void* const* d_in, const int* in_sizes, int n_in,
                              void* d_out, int out_size)
{
    const float* bonds = (const float*)d_in[0];
    const int*   ba1   = (const int*)d_in[1];
    const int*   ba2   = (const int*)d_in[2];
    const float* atoms = (const float*)d_in[3];
    const float* state = (const float*)d_in[4];
    const float* ew1 = (const float*)d_in[5];
    const float* eb1 = (const float*)d_in[6];
    const float* ew2 = (const float*)d_in[7];
    const float* eb2 = (const float*)d_in[8];
    const float* ew3 = (const float*)d_in[9];
    const float* eb3 = (const float*)d_in[10];
    const float* vw1 = (const float*)d_in[11];
    const float* vb1 = (const float*)d_in[12];
    const float* vw2 = (const float*)d_in[13];
    const float* vb2 = (const float*)d_in[14];
    const float* vw3 = (const float*)d_in[15];
    const float* vb3 = (const float*)d_in[16];
    const float* uw1 = (const float*)d_in[17];
    const float* ub1 = (const float*)d_in[18];
    const float* uw2 = (const float*)d_in[19];
    const float* ub2 = (const float*)d_in[20];
    const float* uw3 = (const float*)d_in[21];
    const float* ub3 = (const float*)d_in[22];

    float* out = (float*)d_out;
    float* out_bonds = out;
    float* out_atoms = out + (long)BB * NBND * FF;
    float* out_state = out_atoms + (long)BB * NATM * FF;

    zero_kernel<<<(BB * NATM * FF + 255) / 256, 256>>>();
    atom_pre_kernel<<<(BB * NATM) / 128, 128>>>(atoms, ew1, eb1, state);
    bond_kernel<<<(BB * NBND) / 128, 128>>>(bonds, ba1, ba2,
                                            ew1, ew2, eb2, ew3, eb3, out_bonds);
    atom_main_kernel<<<(BB * NATM) / 128, 128>>>(atoms, state,
                                                 vw1, vb1, vw2, vb2, vw3, vb3, out_atoms);
    reduce_kernel<<<BB * 8, 256>>>(out_atoms);
    state_kernel<<<BB, 64>>>(state, uw1, ub1, uw2, ub2, uw3, ub3, out_state);
}